// round 16
// baseline (speedup 1.0000x reference)
#include <cuda_runtime.h>
#include <math.h>

#define BSZ  1024
#define SLEN 512
#define TT   64
#define KRN  8    // renormalize every KRN unmasked steps (exact pow-2; 8*14.1 < 127 bits safe)

__device__ double g_res[BSZ];
__device__ int    g_cnt[BSZ];
__device__ int    g_ticket;    // zero-init; last block resets to 0 (replay-safe)

static __device__ __forceinline__ unsigned long long pk2(float x, float y) {
    unsigned long long r;
    asm("mov.b64 %0, {%1, %2};" : "=l"(r) : "f"(x), "f"(y));
    return r;
}
static __device__ __forceinline__ float2 upk2(unsigned long long v) {
    float2 r;
    asm("mov.b64 {%0, %1}, %2;" : "=f"(r.x), "=f"(r.y) : "l"(v));
    return r;
}
static __device__ __forceinline__ unsigned long long ffma2(unsigned long long a,
                                                           unsigned long long b,
                                                           unsigned long long c) {
    unsigned long long d;
    asm("fma.rn.f32x2 %0, %1, %2, %3;" : "=l"(d) : "l"(a), "l"(b), "l"(c));
    return d;
}
static __device__ __forceinline__ unsigned long long fadd2(unsigned long long a,
                                                           unsigned long long b) {
    unsigned long long d;
    asm("add.rn.f32x2 %0, %1, %2;" : "=l"(d) : "l"(a), "l"(b));
    return d;
}
static __device__ __forceinline__ unsigned long long fmul2(unsigned long long a,
                                                           unsigned long long b) {
    unsigned long long d;
    asm("mul.rn.f32x2 %0, %1, %2;" : "=l"(d) : "l"(a), "l"(b));
    return d;
}

// One warp (=block) per chain; lane owns adjacent columns c0=2*lane, c1=2*lane+1.
__global__ __launch_bounds__(32, 8)
void crf_forward(const float* __restrict__ e, const int* __restrict__ tags,
                 const unsigned char* __restrict__ mask,
                 const float* __restrict__ st, const float* __restrict__ et,
                 const float* __restrict__ tmat, float* __restrict__ out)
{
    __shared__ unsigned smw[17];   // mask bit-words (512 bits) + zero pad

    const int lane  = threadIdx.x;
    const int chain = blockIdx.x;
    const int c0 = 2 * lane, c1 = c0 + 1;

    const float*         eb = e    + (size_t)chain * (SLEN * TT);
    const int*           tb = tags + chain * SLEN;
    const unsigned char* mb = mask + chain * SLEN;

    // ---- exp(transition) in registers, per-column pair tables ----
    // Ea[m] = (E[2m][c0], E[2m+1][c0]),  Eb[m] = (E[2m][c1], E[2m+1][c1])
    unsigned long long Ea[32], Eb[32];
#pragma unroll
    for (int m = 0; m < 32; ++m) {
        const float2 t0v = *reinterpret_cast<const float2*>(&tmat[(2 * m)     * TT + c0]);
        const float2 t1v = *reinterpret_cast<const float2*>(&tmat[(2 * m + 1) * TT + c0]);
        Ea[m] = pk2(__expf(t0v.x), __expf(t1v.x));
        Eb[m] = pk2(__expf(t0v.y), __expf(t1v.y));
    }

    // ---- tag-path score + mask count + mask bit-words ----
    float scp = 0.f;
    int cntp = 0;
#pragma unroll 4
    for (int k2 = 0; k2 < 16; ++k2) {
        int s = k2 * 32 + lane;
        int m = mb[s];
        unsigned blt = __ballot_sync(0xffffffffu, m != 0);
        if (lane == 0) smw[k2] = blt;
        cntp += m;
        if (s > 0 && m) {
            int tp = tb[s - 1], tn = tb[s];
            scp += __ldg(&tmat[tp * TT + tn]) + eb[s * TT + tn];
        }
    }
    if (lane == 0) smw[16] = 0u;
#pragma unroll
    for (int off = 16; off; off >>= 1) {
        scp  += __shfl_xor_sync(0xffffffffu, scp, off);
        cntp += __shfl_xor_sync(0xffffffffu, cntp, off);
    }
    int   t0    = tb[0];
    int   tlast = tb[cntp - 1];
    float score = scp + st[t0] + eb[t0] + et[tlast];

    // ---- forward-vector init (step 0) ----
    float2 ev0 = *reinterpret_cast<const float2*>(eb + c0);
    float n0 = st[c0] + ev0.x;
    float n1 = st[c1] + ev0.y;
    float base = fmaxf(n0, n1);
#pragma unroll
    for (int off = 16; off; off >>= 1)
        base = fmaxf(base, __shfl_xor_sync(0xffffffffu, base, off));
    float p0 = __expf(n0 - base);
    float p1 = __expf(n1 - base);
    unsigned long long pq = pk2(p0, p1);   // p lives ONLY in registers
    int Eacc = 0;   // accumulated power-of-two scale (exact)
    int rc   = 0;   // unmasked steps since last renorm
    __syncwarp();   // smw visibility

    // F loader: exp computed at PREFETCH time (MUFU latency hidden by distance-4)
    auto ldF = [&](int s) -> unsigned long long {
        const float2 ev = *reinterpret_cast<const float2*>(eb + s * TT + c0);
        return pk2(__expf(ev.x), __expf(ev.y));
    };

    // one step, branchless: q_c = (sum_i p_i E[i][c]) * F_c; SEL keeps old p if masked
    auto do_step = [&](unsigned long long Fpk, unsigned mk) {
        unsigned long long x0 = 0ull, x1 = 0ull, x2 = 0ull, x3 = 0ull;
        unsigned long long y0 = 0ull, y1 = 0ull, y2 = 0ull, y3 = 0ull;
#pragma unroll
        for (int m = 0; m < 32; m += 4) {
            unsigned long long u0 = __shfl_sync(0xffffffffu, pq, m);
            unsigned long long u1 = __shfl_sync(0xffffffffu, pq, m + 1);
            unsigned long long u2 = __shfl_sync(0xffffffffu, pq, m + 2);
            unsigned long long u3 = __shfl_sync(0xffffffffu, pq, m + 3);
            x0 = ffma2(u0, Ea[m],     x0);  y0 = ffma2(u0, Eb[m],     y0);
            x1 = ffma2(u1, Ea[m + 1], x1);  y1 = ffma2(u1, Eb[m + 1], y1);
            x2 = ffma2(u2, Ea[m + 2], x2);  y2 = ffma2(u2, Eb[m + 2], y2);
            x3 = ffma2(u3, Ea[m + 3], x3);  y3 = ffma2(u3, Eb[m + 3], y3);
        }
        float2 qa = upk2(fadd2(fadd2(x0, x1), fadd2(x2, x3)));
        float2 qb = upk2(fadd2(fadd2(y0, y1), fadd2(y2, y3)));
        float2 Fv = upk2(Fpk);
        float q0 = (qa.x + qa.y) * Fv.x;
        float q1 = (qb.x + qb.y) * Fv.y;
        // masked step -> keep old p (select, no branch)
        q0 = mk ? q0 : p0;
        q1 = mk ? q1 : p1;
        rc += mk ? 1 : 0;
        if (rc >= KRN) {                    // exact pow-2 renorm, applied immediately
            rc = 0;
            unsigned mxu = __reduce_max_sync(0xffffffffu,
                                             __float_as_uint(fmaxf(q0, q1)));
            int ke = (int)(mxu >> 23) - 127;               // floor(log2(max q))
            Eacc += ke;
            float rinv = __int_as_float((127 - ke) << 23); // exact 2^-ke
            q0 *= rinv;
            q1 *= rinv;
        }
        p0 = q0;
        p1 = q1;
        pq = pk2(q0, q1);
    };

    // ---- main loop: prefetch distance 4 (F precomputed), unrolled x4 ----
    unsigned long long FA = ldF(1);
    unsigned long long FB = ldF(2);
    unsigned long long FC = ldF(3);
    unsigned long long FD = ldF(4);
#pragma unroll 1
    for (int s = 1; s < SLEN; s += 4) {
        unsigned long long cA = FA, cB = FB, cC = FC, cD = FD;
        unsigned w0 = smw[s >> 5];
        unsigned w1 = smw[(s + 3) >> 5];
        unsigned mb4 = __funnelshift_r(w0, w1, s & 31);
        if (s + 4 < SLEN) FA = ldF(s + 4);
        if (s + 5 < SLEN) FB = ldF(s + 5);
        if (s + 6 < SLEN) FC = ldF(s + 6);
        if (s + 7 < SLEN) FD = ldF(s + 7);
        do_step(cA, mb4 & 1u);
        if (s + 1 < SLEN) do_step(cB, mb4 & 2u);
        if (s + 2 < SLEN) do_step(cC, mb4 & 4u);
        if (s + 3 < SLEN) do_step(cD, mb4 & 8u);
    }

    // ---- logZ, per-chain result ----
    float z = p0 * __expf(et[c0]) + p1 * __expf(et[c1]);
#pragma unroll
    for (int off = 16; off; off >>= 1)
        z += __shfl_xor_sync(0xffffffffu, z, off);
    if (lane == 0) {
        double logZ = (double)base + (double)Eacc * 0.6931471805599453094
                    + log((double)z);
        g_res[chain] = (double)score - logZ;
        g_cnt[chain] = cntp;
    }

    // ---- last-block fused finalization (single warp, deterministic order) ----
    __syncwarp();
    int tkt = 0;
    if (lane == 0) {
        __threadfence();
        tkt = atomicAdd(&g_ticket, 1);
    }
    tkt = __shfl_sync(0xffffffffu, tkt, 0);
    if (tkt == (int)gridDim.x - 1) {
        __threadfence();
        double acc = 0.0;
        int    cnt = 0;
#pragma unroll
        for (int i = 0; i < BSZ / 32; ++i) {   // 32 chains per lane
            int idx = lane + i * 32;
            acc += g_res[idx];
            cnt += g_cnt[idx];
        }
#pragma unroll
        for (int off = 16; off; off >>= 1) {
            acc += __shfl_xor_sync(0xffffffffu, acc, off);
            cnt += __shfl_xor_sync(0xffffffffu, cnt, off);
        }
        if (lane == 0) {
            out[0] = (float)(acc / (double)cnt);
            g_ticket = 0;                      // reset for next graph replay
        }
    }
}

extern "C" void kernel_launch(void* const* d_in, const int* in_sizes, int n_in,
                              void* d_out, int out_size)
{
    const float*         e    = (const float*)d_in[0];
    const int*           tags = (const int*)d_in[1];
    const unsigned char* mask = (const unsigned char*)d_in[2];
    const float*         st   = (const float*)d_in[3];
    const float*         et   = (const float*)d_in[4];
    const float*         t    = (const float*)d_in[5];

    crf_forward<<<BSZ, 32>>>(e, tags, mask, st, et, t, (float*)d_out);
}